// round 1
// baseline (speedup 1.0000x reference)
#include <cuda_runtime.h>

// CDEModel: neural CDE, B=128, SEG=64, C_IN=32, H=128, W_MLP=128, C_OUT=1.
// Inputs (metadata order): coeffs, W1, b1, W2, b2, W3, b3, Wi, bi, Wr, br.
// One CTA handles 2 batch rows; 64 CTAs; 512 threads.

#define NTHREADS 512

__device__ __forceinline__ float fast_tanh(float x){
    // tanh(x) = 1 - 2/(e^{2x}+1); __expf handles +/-inf saturation correctly.
    float e = __expf(2.0f * x);
    return 1.0f - 2.0f / (e + 1.0f);
}

__global__ __launch_bounds__(NTHREADS)
void cde_kernel(const float* __restrict__ coeffs,
                const float* __restrict__ W1, const float* __restrict__ b1,
                const float* __restrict__ W2, const float* __restrict__ b2,
                const float* __restrict__ W3, const float* __restrict__ b3,
                const float* __restrict__ Wi, const float* __restrict__ bi,
                const float* __restrict__ Wr, const float* __restrict__ br,
                float* __restrict__ out)
{
    // activations as row pairs: .x = row0 (2*blk), .y = row1 (2*blk+1)
    __shared__ float2 zs[128], ys[128], h1s[128], h2s[128], ks[128], dzs[128];
    __shared__ float2 dx1[32], dx23[32], dx4[32];

    const int tid = threadIdx.x;
    const int blk = blockIdx.x;   // batch rows 2*blk, 2*blk+1

    // ---- init: z0 = ca[:,0] @ Wi + bi ----
    if (tid < 256){
        int row = tid >> 7, j = tid & 127;
        const float* cf = coeffs + ((size_t)(2*blk + row) * 64) * 128;  // seg 0
        float acc = bi[j];
        #pragma unroll 8
        for (int c = 0; c < 32; c++)
            acc = fmaf(cf[c], Wi[c*128 + j], acc);
        ((float*)&zs[j])[row] = acc;
        ((float*)&ys[j])[row] = acc;
        ((float*)&ks[j])[row] = 0.0f;
    }
    __syncthreads();

    for (int s = 0; s < 64; s++){
        // ---- spline derivative dX at f=0, f=0.5, f=1(next knot) ----
        if (tid < 64){
            int row = tid >> 5, c = tid & 31;
            const float* cf = coeffs + ((size_t)(2*blk + row) * 64 + s) * 128;
            float cb = cf[32+c], c2 = cf[64+c], c3 = cf[96+c];
            ((float*)&dx1[c])[row]  = cb;                              // f = 0
            ((float*)&dx23[c])[row] = cb + 0.5f*c2 + 0.25f*c3;         // f = 0.5
            float d4 = (s < 63) ? cf[128 + 32 + c]                     // next seg, f=0
                                : (cb + c2 + c3);                      // s=63, f=1
            ((float*)&dx4[c])[row]  = d4;
        }
        __syncthreads();

        #pragma unroll 1
        for (int stage = 0; stage < 4; stage++){
            // ---- layer 1: h1 = relu(y @ W1 + b1) ----
            if (tid < 256){
                int row = tid >> 7, j = tid & 127;
                float acc = b1[j];
                #pragma unroll 4
                for (int k = 0; k < 128; k++)
                    acc = fmaf(((const float*)&ys[k])[row], W1[k*128 + j], acc);
                ((float*)&h1s[j])[row] = fmaxf(acc, 0.0f);
            }
            __syncthreads();
            // ---- layer 2: h2 = relu(h1 @ W2 + b2) ----
            if (tid < 256){
                int row = tid >> 7, j = tid & 127;
                float acc = b2[j];
                #pragma unroll 4
                for (int k = 0; k < 128; k++)
                    acc = fmaf(((const float*)&h1s[k])[row], W2[k*128 + j], acc);
                ((float*)&h2s[j])[row] = fmaxf(acc, 0.0f);
            }
            __syncthreads();

            // ---- layer 3 + tanh + contraction dz[h] = sum_c tanh(h3[h,c]) dX[c] ----
            const float2* dxp = (stage == 0) ? dx1 : ((stage == 3) ? dx4 : dx23);
            #pragma unroll 1
            for (int pass = 0; pass < 2; pass++){
                int j4 = pass*2048 + tid*4;               // 4 consecutive cols, same h
                const float4 bb = *reinterpret_cast<const float4*>(b3 + j4);
                float a0 = bb.x, a1 = bb.y, a2 = bb.z, a3 = bb.w;   // row0
                float e0 = bb.x, e1 = bb.y, e2 = bb.z, e3 = bb.w;   // row1
                const float4* wrow = reinterpret_cast<const float4*>(W3) + (j4 >> 2);
                #pragma unroll 4
                for (int k = 0; k < 128; k++){
                    float4 w = wrow[k << 10];             // W3[k][j4..j4+3]
                    float2 h = h2s[k];                    // broadcast LDS.64
                    a0 = fmaf(w.x, h.x, a0); e0 = fmaf(w.x, h.y, e0);
                    a1 = fmaf(w.y, h.x, a1); e1 = fmaf(w.y, h.y, e1);
                    a2 = fmaf(w.z, h.x, a2); e2 = fmaf(w.z, h.y, e2);
                    a3 = fmaf(w.w, h.x, a3); e3 = fmaf(w.w, h.y, e3);
                }
                int c0 = j4 & 31;
                float2 d0 = dxp[c0], d1 = dxp[c0+1], d2 = dxp[c0+2], d3 = dxp[c0+3];
                float pr0 = fast_tanh(a0)*d0.x + fast_tanh(a1)*d1.x
                          + fast_tanh(a2)*d2.x + fast_tanh(a3)*d3.x;
                float pr1 = fast_tanh(e0)*d0.y + fast_tanh(e1)*d1.y
                          + fast_tanh(e2)*d2.y + fast_tanh(e3)*d3.y;
                // 8 lanes (32 cols) share one h: butterfly down within octet
                #pragma unroll
                for (int off = 4; off >= 1; off >>= 1){
                    pr0 += __shfl_down_sync(0xffffffffu, pr0, off);
                    pr1 += __shfl_down_sync(0xffffffffu, pr1, off);
                }
                if ((tid & 7) == 0)
                    dzs[j4 >> 5] = make_float2(pr0, pr1);
            }
            __syncthreads();

            // ---- RK4 stage update ----
            if (tid < 256){
                int row = tid >> 7, j = tid & 127;
                float d  = ((const float*)&dzs[j])[row];
                float kw = (stage == 0 || stage == 3) ? 1.0f : 2.0f;
                float kv = ((const float*)&ks[j])[row] + kw * d;
                ((float*)&ks[j])[row] = kv;
                if (stage < 3){
                    float a = (stage == 2) ? 1.0f : 0.5f;
                    ((float*)&ys[j])[row] = ((const float*)&zs[j])[row] + a * d;
                } else {
                    float zn = ((const float*)&zs[j])[row] + kv * (1.0f/6.0f);
                    ((float*)&zs[j])[row] = zn;
                    ((float*)&ys[j])[row] = zn;
                    ((float*)&ks[j])[row] = 0.0f;
                }
            }
            __syncthreads();
        }
    }

    // ---- readout: sigmoid(z @ Wr + br) ----
    if (tid < 64){
        int row = tid >> 5, lane = tid & 31;
        float partial = 0.0f;
        #pragma unroll
        for (int h = lane; h < 128; h += 32)
            partial = fmaf(((const float*)&zs[h])[row], Wr[h], partial);
        #pragma unroll
        for (int off = 16; off >= 1; off >>= 1)
            partial += __shfl_down_sync(0xffffffffu, partial, off);
        if (lane == 0)
            out[2*blk + row] = 1.0f / (1.0f + __expf(-(partial + br[0])));
    }
}

extern "C" void kernel_launch(void* const* d_in, const int* in_sizes, int n_in,
                              void* d_out, int out_size)
{
    const float* coeffs = (const float*)d_in[0];
    const float* W1 = (const float*)d_in[1];
    const float* b1 = (const float*)d_in[2];
    const float* W2 = (const float*)d_in[3];
    const float* b2 = (const float*)d_in[4];
    const float* W3 = (const float*)d_in[5];
    const float* b3 = (const float*)d_in[6];
    const float* Wi = (const float*)d_in[7];
    const float* bi = (const float*)d_in[8];
    const float* Wr = (const float*)d_in[9];
    const float* br = (const float*)d_in[10];
    float* out = (float*)d_out;

    cde_kernel<<<64, NTHREADS>>>(coeffs, W1, b1, W2, b2, W3, b3,
                                 Wi, bi, Wr, br, out);
}

// round 2
// speedup vs baseline: 1.0073x; 1.0073x over previous
#include <cuda_runtime.h>

// CDEModel: neural CDE, B=128, SEG=64, C_IN=32, H=128, W_MLP=128, C_OUT=1.
// Inputs (metadata order): coeffs, W1, b1, W2, b2, W3, b3, Wi, bi, Wr, br.
// One CTA handles 2 batch rows; 64 CTAs; 512 threads.

#define NTHREADS 512

__device__ __forceinline__ float fast_tanh(float x){
    // tanh(x) = 1 - 2/(e^{2x}+1); __expf handles +/-inf saturation correctly.
    float e = __expf(2.0f * x);
    return 1.0f - 2.0f / (e + 1.0f);
}

__global__ __launch_bounds__(NTHREADS)
void cde_kernel(const float* __restrict__ coeffs,
                const float* __restrict__ W1, const float* __restrict__ b1,
                const float* __restrict__ W2, const float* __restrict__ b2,
                const float* __restrict__ W3, const float* __restrict__ b3,
                const float* __restrict__ Wi, const float* __restrict__ bi,
                const float* __restrict__ Wr, const float* __restrict__ br,
                float* __restrict__ out)
{
    // activations as row pairs: .x = row0 (2*blk), .y = row1 (2*blk+1)
    __shared__ float2 zs[128], ys[128], h1s[128], h2s[128], ks[128], dzs[128];
    __shared__ float2 dx1[32], dx23[32], dx4[32];

    const int tid = threadIdx.x;
    const int blk = blockIdx.x;   // batch rows 2*blk, 2*blk+1

    // ---- init: z0 = ca[:,0] @ Wi + bi ----
    if (tid < 256){
        int row = tid >> 7, j = tid & 127;
        const float* cf = coeffs + ((size_t)(2*blk + row) * 64) * 128;  // seg 0
        float acc = bi[j];
        #pragma unroll 8
        for (int c = 0; c < 32; c++)
            acc = fmaf(cf[c], Wi[c*128 + j], acc);
        ((float*)&zs[j])[row] = acc;
        ((float*)&ys[j])[row] = acc;
        ((float*)&ks[j])[row] = 0.0f;
    }
    __syncthreads();

    for (int s = 0; s < 64; s++){
        // ---- spline derivative dX at f=0, f=0.5, f=1(next knot) ----
        if (tid < 64){
            int row = tid >> 5, c = tid & 31;
            const float* cf = coeffs + ((size_t)(2*blk + row) * 64 + s) * 128;
            float cb = cf[32+c], c2 = cf[64+c], c3 = cf[96+c];
            ((float*)&dx1[c])[row]  = cb;                              // f = 0
            ((float*)&dx23[c])[row] = cb + 0.5f*c2 + 0.25f*c3;         // f = 0.5
            float d4 = (s < 63) ? cf[128 + 32 + c]                     // next seg, f=0
                                : (cb + c2 + c3);                      // s=63, f=1
            ((float*)&dx4[c])[row]  = d4;
        }
        __syncthreads();

        #pragma unroll 1
        for (int stage = 0; stage < 4; stage++){
            // ---- layer 1: h1 = relu(y @ W1 + b1) ----
            if (tid < 256){
                int row = tid >> 7, j = tid & 127;
                float acc = b1[j];
                #pragma unroll 4
                for (int k = 0; k < 128; k++)
                    acc = fmaf(((const float*)&ys[k])[row], W1[k*128 + j], acc);
                ((float*)&h1s[j])[row] = fmaxf(acc, 0.0f);
            }
            __syncthreads();
            // ---- layer 2: h2 = relu(h1 @ W2 + b2) ----
            if (tid < 256){
                int row = tid >> 7, j = tid & 127;
                float acc = b2[j];
                #pragma unroll 4
                for (int k = 0; k < 128; k++)
                    acc = fmaf(((const float*)&h1s[k])[row], W2[k*128 + j], acc);
                ((float*)&h2s[j])[row] = fmaxf(acc, 0.0f);
            }
            __syncthreads();

            // ---- layer 3 + tanh + contraction dz[h] = sum_c tanh(h3[h,c]) dX[c] ----
            const float2* dxp = (stage == 0) ? dx1 : ((stage == 3) ? dx4 : dx23);
            #pragma unroll 1
            for (int pass = 0; pass < 2; pass++){
                int j4 = pass*2048 + tid*4;               // 4 consecutive cols, same h
                const float4 bb = *reinterpret_cast<const float4*>(b3 + j4);
                float a0 = bb.x, a1 = bb.y, a2 = bb.z, a3 = bb.w;   // row0
                float e0 = bb.x, e1 = bb.y, e2 = bb.z, e3 = bb.w;   // row1
                const float4* wrow = reinterpret_cast<const float4*>(W3) + (j4 >> 2);
                #pragma unroll 4
                for (int k = 0; k < 128; k++){
                    float4 w = wrow[k << 10];             // W3[k][j4..j4+3]
                    float2 h = h2s[k];                    // broadcast LDS.64
                    a0 = fmaf(w.x, h.x, a0); e0 = fmaf(w.x, h.y, e0);
                    a1 = fmaf(w.y, h.x, a1); e1 = fmaf(w.y, h.y, e1);
                    a2 = fmaf(w.z, h.x, a2); e2 = fmaf(w.z, h.y, e2);
                    a3 = fmaf(w.w, h.x, a3); e3 = fmaf(w.w, h.y, e3);
                }
                int c0 = j4 & 31;
                float2 d0 = dxp[c0], d1 = dxp[c0+1], d2 = dxp[c0+2], d3 = dxp[c0+3];
                float pr0 = fast_tanh(a0)*d0.x + fast_tanh(a1)*d1.x
                          + fast_tanh(a2)*d2.x + fast_tanh(a3)*d3.x;
                float pr1 = fast_tanh(e0)*d0.y + fast_tanh(e1)*d1.y
                          + fast_tanh(e2)*d2.y + fast_tanh(e3)*d3.y;
                // 8 lanes (32 cols) share one h: butterfly down within octet
                #pragma unroll
                for (int off = 4; off >= 1; off >>= 1){
                    pr0 += __shfl_down_sync(0xffffffffu, pr0, off);
                    pr1 += __shfl_down_sync(0xffffffffu, pr1, off);
                }
                if ((tid & 7) == 0)
                    dzs[j4 >> 5] = make_float2(pr0, pr1);
            }
            __syncthreads();

            // ---- RK4 stage update ----
            if (tid < 256){
                int row = tid >> 7, j = tid & 127;
                float d  = ((const float*)&dzs[j])[row];
                float kw = (stage == 0 || stage == 3) ? 1.0f : 2.0f;
                float kv = ((const float*)&ks[j])[row] + kw * d;
                ((float*)&ks[j])[row] = kv;
                if (stage < 3){
                    float a = (stage == 2) ? 1.0f : 0.5f;
                    ((float*)&ys[j])[row] = ((const float*)&zs[j])[row] + a * d;
                } else {
                    float zn = ((const float*)&zs[j])[row] + kv * (1.0f/6.0f);
                    ((float*)&zs[j])[row] = zn;
                    ((float*)&ys[j])[row] = zn;
                    ((float*)&ks[j])[row] = 0.0f;
                }
            }
            __syncthreads();
        }
    }

    // ---- readout: sigmoid(z @ Wr + br) ----
    if (tid < 64){
        int row = tid >> 5, lane = tid & 31;
        float partial = 0.0f;
        #pragma unroll
        for (int h = lane; h < 128; h += 32)
            partial = fmaf(((const float*)&zs[h])[row], Wr[h], partial);
        #pragma unroll
        for (int off = 16; off >= 1; off >>= 1)
            partial += __shfl_down_sync(0xffffffffu, partial, off);
        if (lane == 0)
            out[2*blk + row] = 1.0f / (1.0f + __expf(-(partial + br[0])));
    }
}

extern "C" void kernel_launch(void* const* d_in, const int* in_sizes, int n_in,
                              void* d_out, int out_size)
{
    const float* coeffs = (const float*)d_in[0];
    const float* W1 = (const float*)d_in[1];
    const float* b1 = (const float*)d_in[2];
    const float* W2 = (const float*)d_in[3];
    const float* b2 = (const float*)d_in[4];
    const float* W3 = (const float*)d_in[5];
    const float* b3 = (const float*)d_in[6];
    const float* Wi = (const float*)d_in[7];
    const float* bi = (const float*)d_in[8];
    const float* Wr = (const float*)d_in[9];
    const float* br = (const float*)d_in[10];
    float* out = (float*)d_out;

    cde_kernel<<<64, NTHREADS>>>(coeffs, W1, b1, W2, b2, W3, b3,
                                 Wi, bi, Wr, br, out);
}

// round 3
// speedup vs baseline: 2.5692x; 2.5506x over previous
#include <cuda_runtime.h>

// Persistent neural-CDE kernel. 128 CTAs (one per batch row AND one per
// hidden unit h), 512 threads. W3 column-slice (16KB) + W1 + W2 resident in
// smem. Cross-CTA exchange of h2 / dz / dX via __device__ buffers with
// software grid barriers (2 per RK4 stage eval, 512 total).

#define NCTAS 128
#define NT    512

__device__ float g_h2T[128 * 128];   // [k][r]
__device__ float g_dz [128 * 128];   // [r][h]
__device__ float g_dx [128 * 3 * 32];// [r][sel][c]
__device__ unsigned int g_cnt;       // barrier arrivals (self-resetting)
__device__ unsigned int g_gen;       // barrier generation (monotonic)

__device__ __forceinline__ void grid_barrier()
{
    __syncthreads();
    if (threadIdx.x == 0) {
        unsigned int gen, old;
        asm volatile("ld.acquire.gpu.b32 %0, [%1];" : "=r"(gen) : "l"(&g_gen));
        __threadfence();   // publish CTA writes (gpu scope -> CCTL.IVALL)
        asm volatile("atom.acq_rel.gpu.add.u32 %0, [%1], %2;"
                     : "=r"(old) : "l"(&g_cnt), "r"(1u) : "memory");
        if (old == NCTAS - 1u) {
            asm volatile("st.relaxed.gpu.b32 [%0], %1;" :: "l"(&g_cnt), "r"(0u) : "memory");
            asm volatile("red.release.gpu.add.u32 [%0], %1;" :: "l"(&g_gen), "r"(1u) : "memory");
        } else {
            unsigned int g2;
            do {
                asm volatile("ld.acquire.gpu.b32 %0, [%1];" : "=r"(g2) : "l"(&g_gen) : "memory");
            } while (g2 == gen);
        }
        __threadfence();   // invalidate L1 so we see peers' writes
    }
    __syncthreads();
}

// h1/h2 GEMV: out[j] = relu(b[j] + sum_k v[k] * W[k][j]); W,b,v,out in smem.
__device__ __forceinline__ void gemv128(const float* __restrict__ vs,
                                        const float* __restrict__ Wsm,
                                        const float* __restrict__ bsm,
                                        float* __restrict__ outv,
                                        float* __restrict__ sp)
{
    const int tid = threadIdx.x;
    const int jq = tid & 31, kc = tid >> 5;     // 32 col-quads x 16 k-chunks
    const int k0 = kc << 3;
    float4 acc = make_float4(0.f, 0.f, 0.f, 0.f);
    #pragma unroll
    for (int kk = 0; kk < 8; kk++) {
        int k = k0 + kk;
        float v = vs[k];
        float4 w = *(const float4*)(Wsm + k * 128 + jq * 4);
        acc.x = fmaf(v, w.x, acc.x);
        acc.y = fmaf(v, w.y, acc.y);
        acc.z = fmaf(v, w.z, acc.z);
        acc.w = fmaf(v, w.w, acc.w);
    }
    *(float4*)(sp + ((kc << 5) + jq) * 4) = acc;
    __syncthreads();
    if (tid < 128) {
        float s = bsm[tid];
        #pragma unroll
        for (int kc2 = 0; kc2 < 16; kc2++)
            s += sp[(kc2 << 7) + tid];
        outv[tid] = fmaxf(s, 0.0f);
    }
    __syncthreads();
}

// cephes-style rational tanh: returns p, writes q; tanh(x) = p/q. FMA-only.
__device__ __forceinline__ float tanh_pq(float x, float& qo)
{
    x = fminf(fmaxf(x, -7.90531110591164f), 7.90531110591164f);
    float x2 = x * x;
    float p = fmaf(x2, -2.76076847742355e-16f, 2.00018790482477e-13f);
    p = fmaf(p, x2, -8.60467152213735e-11f);
    p = fmaf(p, x2,  5.12229709037114e-08f);
    p = fmaf(p, x2,  1.48572235717979e-05f);
    p = fmaf(p, x2,  6.37261928875436e-04f);
    p = fmaf(p, x2,  4.89352455891786e-03f);
    p = p * x;
    float q = fmaf(x2, 1.19825839466702e-06f, 1.18534705686654e-04f);
    q = fmaf(q, x2, 2.26843463243900e-03f);
    qo = fmaf(q, x2, 4.89352518554385e-03f);
    return p;
}

// batched reciprocal: 1 MUFU per 4 divisions
__device__ __forceinline__ void rcp4(const float* q, float* inv)
{
    float a01 = q[0] * q[1], a23 = q[2] * q[3], P = a01 * a23, R;
    asm("rcp.approx.f32 %0, %1;" : "=f"(R) : "f"(P));
    inv[0] = R * q[1] * a23;
    inv[1] = R * q[0] * a23;
    inv[2] = R * a01 * q[3];
    inv[3] = R * a01 * q[2];
}

// dynamic smem layout (floats):
//  h2s 16384 | w1s 16384 | w2s 16384 | w3s 4096 | sp 2048 |
//  b1s 128 | b2s 128 | ys 128 | zs 128 | kacc 128 | h1s 128 | h2row 128
#define SMEM_FLOATS (16384*3 + 4096 + 2048 + 7*128)
#define SMEM_BYTES  (SMEM_FLOATS * 4)

extern __shared__ float smem[];

__global__ __launch_bounds__(NT, 1)
void cde_kernel(const float* __restrict__ coeffs,
                const float* __restrict__ W1, const float* __restrict__ b1,
                const float* __restrict__ W2, const float* __restrict__ b2,
                const float* __restrict__ W3, const float* __restrict__ b3,
                const float* __restrict__ Wi, const float* __restrict__ bi,
                const float* __restrict__ Wr, const float* __restrict__ br,
                float* __restrict__ out)
{
    float* h2s   = smem;                // [k][r] 128x128
    float* w1s   = h2s  + 16384;        // [k][j]
    float* w2s   = w1s  + 16384;
    float* w3s   = w2s  + 16384;        // [k][c] 128x32 (our h's slice)
    float* sp    = w3s  + 4096;
    float* b1s   = sp   + 2048;
    float* b2s   = b1s  + 128;
    float* ys    = b2s  + 128;
    float* zs    = ys   + 128;
    float* kacc  = zs   + 128;
    float* h1s   = kacc + 128;
    float* h2row = h1s  + 128;

    const int tid = threadIdx.x;
    const int r   = blockIdx.x;         // owned batch row == owned hidden unit h

    // ---- prologue: stage weights into smem ----
    #pragma unroll
    for (int i = 0; i < 8; i++) {
        int idx = tid + i * NT;         // 4096 float4 per matrix
        ((float4*)w1s)[idx] = ((const float4*)W1)[idx];
        ((float4*)w2s)[idx] = ((const float4*)W2)[idx];
    }
    #pragma unroll
    for (int i = 0; i < 2; i++) {       // W3 slice: 1024 float4
        int idx = tid + i * NT;
        int k = idx >> 3, cq = idx & 7;
        *(float4*)(w3s + k * 32 + cq * 4) =
            *(const float4*)(W3 + k * 4096 + r * 32 + cq * 4);
    }
    if (tid < 128) { b1s[tid] = b1[tid]; b2s[tid] = b2[tid]; }

    // z0 = X(0) @ Wi + bi  (X(0) = ca of segment 0)
    if (tid < 128) {
        const float* ca = coeffs + (size_t)r * 8192;
        float acc = bi[tid];
        #pragma unroll
        for (int c = 0; c < 32; c++)
            acc = fmaf(ca[c], Wi[c * 128 + tid], acc);
        zs[tid] = acc; ys[tid] = acc; kacc[tid] = 0.0f;
    }
    __syncthreads();

    // per-thread GEMM constants
    const int cg = tid & 7, rg = tid >> 3;
    const int r0 = rg << 1;
    const float4 b3q = *(const float4*)(b3 + r * 32 + (cg << 2));

    for (int s = 0; s < 64; s++) {
        // publish dX for this segment (dx at f=0, f=0.5, f=1)
        if (tid < 32) {
            const float* base = coeffs + (size_t)r * 8192 + s * 128;
            int c = tid;
            float cb = base[32 + c], c2 = base[64 + c], c3 = base[96 + c];
            g_dx[(r * 3 + 0) * 32 + c] = cb;
            g_dx[(r * 3 + 1) * 32 + c] = fmaf(0.25f, c3, fmaf(0.5f, c2, cb));
            g_dx[(r * 3 + 2) * 32 + c] = (s < 63) ? base[128 + 32 + c]
                                                  : (cb + c2 + c3);
        }

        for (int stage = 0; stage < 4; stage++) {
            // ---- row-owner: layers 1,2 on own row, publish h2 ----
            gemv128(ys,  w1s, b1s, h1s,   sp);
            gemv128(h1s, w2s, b2s, h2row, sp);
            if (tid < 128)
                g_h2T[tid * 128 + r] = h2row[tid];

            grid_barrier();   // A: all h2 rows + dX published

            // ---- stage h2T into smem ----
            #pragma unroll
            for (int i = 0; i < 8; i++)
                ((float4*)h2s)[tid + i * NT] = ((const float4*)g_h2T)[tid + i * NT];
            __syncthreads();

            // ---- h-owner GEMM: h3[r0..r0+1][c0..c0+3], K=128 ----
            float a0 = b3q.x, a1 = b3q.y, a2 = b3q.z, a3 = b3q.w;   // row r0
            float e0 = b3q.x, e1 = b3q.y, e2 = b3q.z, e3 = b3q.w;   // row r0+1
            #pragma unroll 8
            for (int k = 0; k < 128; k++) {
                float2 h = *(const float2*)(h2s + k * 128 + r0);
                float4 w = *(const float4*)(w3s + k * 32 + (cg << 2));
                a0 = fmaf(w.x, h.x, a0); e0 = fmaf(w.x, h.y, e0);
                a1 = fmaf(w.y, h.x, a1); e1 = fmaf(w.y, h.y, e1);
                a2 = fmaf(w.z, h.x, a2); e2 = fmaf(w.z, h.y, e2);
                a3 = fmaf(w.w, h.x, a3); e3 = fmaf(w.w, h.y, e3);
            }

            // ---- tanh (rational, batched rcp) + contraction with dX ----
            float p[8], q[8], inv[8];
            p[0] = tanh_pq(a0, q[0]); p[1] = tanh_pq(a1, q[1]);
            p[2] = tanh_pq(a2, q[2]); p[3] = tanh_pq(a3, q[3]);
            p[4] = tanh_pq(e0, q[4]); p[5] = tanh_pq(e1, q[5]);
            p[6] = tanh_pq(e2, q[6]); p[7] = tanh_pq(e3, q[7]);
            rcp4(q,     inv);
            rcp4(q + 4, inv + 4);

            const int sel = (stage == 0) ? 0 : ((stage == 3) ? 2 : 1);
            float4 dA = *(const float4*)(g_dx + (r0 * 3 + sel) * 32 + (cg << 2));
            float4 dB = *(const float4*)(g_dx + ((r0 + 1) * 3 + sel) * 32 + (cg << 2));
            float pr0 = p[0]*inv[0]*dA.x + p[1]*inv[1]*dA.y
                      + p[2]*inv[2]*dA.z + p[3]*inv[3]*dA.w;
            float pr1 = p[4]*inv[4]*dB.x + p[5]*inv[5]*dB.y
                      + p[6]*inv[6]*dB.z + p[7]*inv[7]*dB.w;
            #pragma unroll
            for (int off = 4; off >= 1; off >>= 1) {
                pr0 += __shfl_down_sync(0xffffffffu, pr0, off);
                pr1 += __shfl_down_sync(0xffffffffu, pr1, off);
            }
            if (cg == 0) {
                g_dz[ r0      * 128 + r] = pr0;
                g_dz[(r0 + 1) * 128 + r] = pr1;
            }

            grid_barrier();   // B: dz complete

            // ---- row-owner: RK4 stage update ----
            if (tid < 32) {
                int h0 = tid << 2;
                float4 dz = *(const float4*)(g_dz + r * 128 + h0);
                float4 kq = *(float4*)(kacc + h0);
                float4 zq = *(float4*)(zs + h0);
                float kw = (stage == 0 || stage == 3) ? 1.0f : 2.0f;
                kq.x = fmaf(kw, dz.x, kq.x); kq.y = fmaf(kw, dz.y, kq.y);
                kq.z = fmaf(kw, dz.z, kq.z); kq.w = fmaf(kw, dz.w, kq.w);
                if (stage < 3) {
                    float aa = (stage == 2) ? 1.0f : 0.5f;
                    float4 yq;
                    yq.x = fmaf(aa, dz.x, zq.x); yq.y = fmaf(aa, dz.y, zq.y);
                    yq.z = fmaf(aa, dz.z, zq.z); yq.w = fmaf(aa, dz.w, zq.w);
                    *(float4*)(ys + h0) = yq;
                    *(float4*)(kacc + h0) = kq;
                } else {
                    const float c6 = 1.0f / 6.0f;
                    zq.x = fmaf(c6, kq.x, zq.x); zq.y = fmaf(c6, kq.y, zq.y);
                    zq.z = fmaf(c6, kq.z, zq.z); zq.w = fmaf(c6, kq.w, zq.w);
                    *(float4*)(zs + h0) = zq;
                    *(float4*)(ys + h0) = zq;
                    *(float4*)(kacc + h0) = make_float4(0.f, 0.f, 0.f, 0.f);
                }
            }
            __syncthreads();
        }
    }

    // ---- readout: out[r] = sigmoid(z @ Wr + br) ----
    if (tid < 32) {
        float part = 0.0f;
        #pragma unroll
        for (int h = tid; h < 128; h += 32)
            part = fmaf(zs[h], Wr[h], part);
        #pragma unroll
        for (int off = 16; off >= 1; off >>= 1)
            part += __shfl_down_sync(0xffffffffu, part, off);
        if (tid == 0)
            out[r] = 1.0f / (1.0f + __expf(-(part + br[0])));
    }
}

extern "C" void kernel_launch(void* const* d_in, const int* in_sizes, int n_in,
                              void* d_out, int out_size)
{
    const float* coeffs = (const float*)d_in[0];
    const float* W1 = (const float*)d_in[1];
    const float* b1 = (const float*)d_in[2];
    const float* W2 = (const float*)d_in[3];
    const float* b2 = (const float*)d_in[4];
    const float* W3 = (const float*)d_in[5];
    const float* b3 = (const float*)d_in[6];
    const float* Wi = (const float*)d_in[7];
    const float* bi = (const float*)d_in[8];
    const float* Wr = (const float*)d_in[9];
    const float* br = (const float*)d_in[10];
    float* out = (float*)d_out;

    cudaFuncSetAttribute(cde_kernel,
                         cudaFuncAttributeMaxDynamicSharedMemorySize, SMEM_BYTES);
    cde_kernel<<<NCTAS, NT, SMEM_BYTES>>>(coeffs, W1, b1, W2, b2, W3, b3,
                                          Wi, bi, Wr, br, out);
}

// round 4
// speedup vs baseline: 2.7265x; 1.0612x over previous
#include <cuda_runtime.h>

// Persistent neural-CDE kernel. 128 CTAs (one per batch row AND one per
// hidden unit h), 512 threads. W1/W2/W3-slice resident in smem. Cross-CTA
// exchange via __device__ buffers with a flag-array grid barrier
// (no contended atomics), 2 barriers per RK4 stage eval.

#define NCTAS 128
#define NT    512

typedef unsigned long long u64;

__device__ float g_h2T[128 * 128];    // [k][r]
__device__ float g_dz [128 * 128];    // [r][h]
__device__ float g_dx [128 * 3 * 32]; // [r][sel][c]
__device__ unsigned int g_slot[128];  // per-CTA arrival counters (monotonic)
__device__ unsigned int g_gen;        // barrier generation (monotonic)

__device__ __forceinline__ void grid_barrier(unsigned int target)
{
    __syncthreads();
    if (blockIdx.x == 0) {
        if (threadIdx.x < 32) {
            if (threadIdx.x == 0) {
                __threadfence();   // release our CTA's writes (gpu scope)
                asm volatile("st.release.gpu.b32 [%0], %1;"
                             :: "l"(g_slot), "r"(target) : "memory");
            }
            const unsigned int* p = g_slot + threadIdx.x * 4;
            unsigned int a, b, c, d; bool ok;
            do {
                asm volatile("ld.relaxed.gpu.v4.b32 {%0,%1,%2,%3}, [%4];"
                             : "=r"(a), "=r"(b), "=r"(c), "=r"(d)
                             : "l"(p) : "memory");
                ok = (a == target) && (b == target) && (c == target) && (d == target);
            } while (!__all_sync(0xffffffffu, ok));
            if (threadIdx.x == 0) {
                asm volatile("fence.acq_rel.gpu;" ::: "memory");
                asm volatile("st.relaxed.gpu.b32 [%0], %1;"
                             :: "l"(&g_gen), "r"(target) : "memory");
            }
        }
    } else {
        if (threadIdx.x == 0) {
            __threadfence();
            asm volatile("st.release.gpu.b32 [%0], %1;"
                         :: "l"(g_slot + blockIdx.x), "r"(target) : "memory");
            unsigned int g;
            do {
                asm volatile("ld.acquire.gpu.b32 %0, [%1];"
                             : "=r"(g) : "l"(&g_gen) : "memory");
            } while (g != target);
        }
    }
    __syncthreads();
}

// GEMV: out[j] = relu(b[j] + sum_k v[k]*W[k][j]); all operands in smem.
// 512 threads: j = tid&127, 4-way k split.
__device__ __forceinline__ void gemv128(const float* __restrict__ vs,
                                        const float* __restrict__ Wsm,
                                        const float* __restrict__ bsm,
                                        float* __restrict__ outv,
                                        float* __restrict__ sp)
{
    const int tid = threadIdx.x;
    const int j = tid & 127, kq = tid >> 7;
    const float* w = Wsm + (kq << 5) * 128 + j;
    const float* v = vs + (kq << 5);
    float acc0 = 0.f, acc1 = 0.f;
    #pragma unroll
    for (int k = 0; k < 32; k += 2) {
        acc0 = fmaf(v[k],     w[ k      * 128], acc0);
        acc1 = fmaf(v[k + 1], w[(k + 1) * 128], acc1);
    }
    sp[(kq << 7) + j] = acc0 + acc1;
    __syncthreads();
    if (tid < 128) {
        float s = bsm[tid] + sp[tid] + sp[128 + tid] + sp[256 + tid] + sp[384 + tid];
        outv[tid] = fmaxf(s, 0.0f);
    }
    __syncthreads();
}

// cephes-style rational tanh: returns p, writes q; tanh(x) = p/q. FMA-only.
__device__ __forceinline__ float tanh_pq(float x, float& qo)
{
    x = fminf(fmaxf(x, -7.90531110591164f), 7.90531110591164f);
    float x2 = x * x;
    float p = fmaf(x2, -2.76076847742355e-16f, 2.00018790482477e-13f);
    p = fmaf(p, x2, -8.60467152213735e-11f);
    p = fmaf(p, x2,  5.12229709037114e-08f);
    p = fmaf(p, x2,  1.48572235717979e-05f);
    p = fmaf(p, x2,  6.37261928875436e-04f);
    p = fmaf(p, x2,  4.89352455891786e-03f);
    p = p * x;
    float q = fmaf(x2, 1.19825839466702e-06f, 1.18534705686654e-04f);
    q = fmaf(q, x2, 2.26843463243900e-03f);
    qo = fmaf(q, x2, 4.89352518554385e-03f);
    return p;
}

// batched reciprocal: 1 MUFU per 4 divisions
__device__ __forceinline__ void rcp4(const float* q, float* inv)
{
    float a01 = q[0] * q[1], a23 = q[2] * q[3], P = a01 * a23, R;
    asm("rcp.approx.f32 %0, %1;" : "=f"(R) : "f"(P));
    inv[0] = R * q[1] * a23;
    inv[1] = R * q[0] * a23;
    inv[2] = R * a01 * q[3];
    inv[3] = R * a01 * q[2];
}

// dynamic smem layout (floats):
//  h2s 16384 | w1s 16384 | w2s 16384 | w3s 4096 | sp 512 |
//  b1s 128 | b2s 128 | ys 128 | zs 128 | kacc 128 | h1s 128 | h2row 128 | misc 16
#define SMEM_FLOATS (16384*3 + 4096 + 512 + 7*128 + 16)
#define SMEM_BYTES  (SMEM_FLOATS * 4)

extern __shared__ float smem[];

__global__ __launch_bounds__(NT, 1)
void cde_kernel(const float* __restrict__ coeffs,
                const float* __restrict__ W1, const float* __restrict__ b1,
                const float* __restrict__ W2, const float* __restrict__ b2,
                const float* __restrict__ W3, const float* __restrict__ b3,
                const float* __restrict__ Wi, const float* __restrict__ bi,
                const float* __restrict__ Wr, const float* __restrict__ br,
                float* __restrict__ out)
{
    float* h2s   = smem;                // [k][r] 128x128
    float* w1s   = h2s  + 16384;        // [k][j]
    float* w2s   = w1s  + 16384;
    float* w3s   = w2s  + 16384;        // [k][c] 128x32 (our h's slice)
    float* sp    = w3s  + 4096;
    float* b1s   = sp   + 512;
    float* b2s   = b1s  + 128;
    float* ys    = b2s  + 128;
    float* zs    = ys   + 128;
    float* kacc  = zs   + 128;
    float* h1s   = kacc + 128;
    float* h2row = h1s  + 128;
    unsigned int* sbase = (unsigned int*)(h2row + 128);

    const int tid = threadIdx.x;
    const int r   = blockIdx.x;         // owned batch row == owned hidden unit h

    // barrier base (monotonic across graph replays); stable at launch start
    if (tid == 0) {
        unsigned int g0;
        asm volatile("ld.relaxed.gpu.b32 %0, [%1];" : "=r"(g0) : "l"(&g_gen));
        *sbase = g0;
    }

    // ---- prologue: stage weights into smem ----
    #pragma unroll
    for (int i = 0; i < 8; i++) {
        int idx = tid + i * NT;         // 4096 float4 per matrix
        ((float4*)w1s)[idx] = ((const float4*)W1)[idx];
        ((float4*)w2s)[idx] = ((const float4*)W2)[idx];
    }
    #pragma unroll
    for (int i = 0; i < 2; i++) {       // W3 slice: 1024 float4
        int idx = tid + i * NT;
        int k = idx >> 3, cq = idx & 7;
        *(float4*)(w3s + k * 32 + cq * 4) =
            *(const float4*)(W3 + k * 4096 + r * 32 + cq * 4);
    }
    if (tid < 128) { b1s[tid] = b1[tid]; b2s[tid] = b2[tid]; }

    // z0 = X(0) @ Wi + bi
    if (tid < 128) {
        const float* ca = coeffs + (size_t)r * 8192;
        float acc = bi[tid];
        #pragma unroll
        for (int c = 0; c < 32; c++)
            acc = fmaf(ca[c], Wi[c * 128 + tid], acc);
        zs[tid] = acc; ys[tid] = acc; kacc[tid] = 0.0f;
    }
    __syncthreads();

    const unsigned int base = *sbase;
    unsigned int bno = 0;

    // per-thread GEMM constants
    const int cg = tid & 7, rg = tid >> 3;
    const int r0 = rg << 1;
    const float4 b3q = *(const float4*)(b3 + r * 32 + (cg << 2));
    u64 B01, B23;
    asm("mov.b64 %0, {%1,%2};" : "=l"(B01) : "f"(b3q.x), "f"(b3q.y));
    asm("mov.b64 %0, {%1,%2};" : "=l"(B23) : "f"(b3q.z), "f"(b3q.w));

    for (int s = 0; s < 64; s++) {
        // publish dX for this segment (f=0, f=0.5, f=1)
        if (tid < 32) {
            const float* base_c = coeffs + (size_t)r * 8192 + s * 128;
            int c = tid;
            float cb = base_c[32 + c], c2 = base_c[64 + c], c3 = base_c[96 + c];
            g_dx[(r * 3 + 0) * 32 + c] = cb;
            g_dx[(r * 3 + 1) * 32 + c] = fmaf(0.25f, c3, fmaf(0.5f, c2, cb));
            g_dx[(r * 3 + 2) * 32 + c] = (s < 63) ? base_c[128 + 32 + c]
                                                  : (cb + c2 + c3);
        }

        for (int stage = 0; stage < 4; stage++) {
            // ---- row-owner: layers 1,2 on own row, publish h2 ----
            gemv128(ys,  w1s, b1s, h1s,   sp);
            gemv128(h1s, w2s, b2s, h2row, sp);
            if (tid < 128)
                g_h2T[tid * 128 + r] = h2row[tid];

            grid_barrier(base + (++bno));   // A: all h2 rows + dX published

            // ---- stage h2T into smem ----
            #pragma unroll
            for (int i = 0; i < 8; i++)
                ((float4*)h2s)[tid + i * NT] = ((const float4*)g_h2T)[tid + i * NT];
            __syncthreads();

            // ---- h-owner GEMM via packed f32x2 FMA ----
            u64 A01 = B01, A23 = B23;   // row r0,   cols (0,1) (2,3)
            u64 E01 = B01, E23 = B23;   // row r0+1
            const float* wp = w3s + (cg << 2);
            const float* hp = h2s + r0;
            #pragma unroll 8
            for (int k = 0; k < 128; k++) {
                float2 h = *(const float2*)(hp + k * 128);
                float4 w = *(const float4*)(wp + k * 32);
                u64 w01, w23, hx2, hy2;
                asm("mov.b64 %0, {%1,%2};" : "=l"(w01) : "f"(w.x), "f"(w.y));
                asm("mov.b64 %0, {%1,%2};" : "=l"(w23) : "f"(w.z), "f"(w.w));
                asm("mov.b64 %0, {%1,%1};" : "=l"(hx2) : "f"(h.x));
                asm("mov.b64 %0, {%1,%1};" : "=l"(hy2) : "f"(h.y));
                asm("fma.rn.f32x2 %0, %1, %2, %0;" : "+l"(A01) : "l"(w01), "l"(hx2));
                asm("fma.rn.f32x2 %0, %1, %2, %0;" : "+l"(A23) : "l"(w23), "l"(hx2));
                asm("fma.rn.f32x2 %0, %1, %2, %0;" : "+l"(E01) : "l"(w01), "l"(hy2));
                asm("fma.rn.f32x2 %0, %1, %2, %0;" : "+l"(E23) : "l"(w23), "l"(hy2));
            }
            float a0, a1, a2, a3, e0, e1, e2, e3;
            asm("mov.b64 {%0,%1}, %2;" : "=f"(a0), "=f"(a1) : "l"(A01));
            asm("mov.b64 {%0,%1}, %2;" : "=f"(a2), "=f"(a3) : "l"(A23));
            asm("mov.b64 {%0,%1}, %2;" : "=f"(e0), "=f"(e1) : "l"(E01));
            asm("mov.b64 {%0,%1}, %2;" : "=f"(e2), "=f"(e3) : "l"(E23));

            // ---- tanh (rational, batched rcp) + contraction with dX ----
            float p[8], q[8], inv[8];
            p[0] = tanh_pq(a0, q[0]); p[1] = tanh_pq(a1, q[1]);
            p[2] = tanh_pq(a2, q[2]); p[3] = tanh_pq(a3, q[3]);
            p[4] = tanh_pq(e0, q[4]); p[5] = tanh_pq(e1, q[5]);
            p[6] = tanh_pq(e2, q[6]); p[7] = tanh_pq(e3, q[7]);
            rcp4(q,     inv);
            rcp4(q + 4, inv + 4);

            const int sel = (stage == 0) ? 0 : ((stage == 3) ? 2 : 1);
            float4 dA = *(const float4*)(g_dx + (r0 * 3 + sel) * 32 + (cg << 2));
            float4 dB = *(const float4*)(g_dx + ((r0 + 1) * 3 + sel) * 32 + (cg << 2));
            float pr0 = p[0]*inv[0]*dA.x + p[1]*inv[1]*dA.y
                      + p[2]*inv[2]*dA.z + p[3]*inv[3]*dA.w;
            float pr1 = p[4]*inv[4]*dB.x + p[5]*inv[5]*dB.y
                      + p[6]*inv[6]*dB.z + p[7]*inv[7]*dB.w;
            #pragma unroll
            for (int off = 4; off >= 1; off >>= 1) {
                pr0 += __shfl_down_sync(0xffffffffu, pr0, off);
                pr1 += __shfl_down_sync(0xffffffffu, pr1, off);
            }
            if (cg == 0) {
                g_dz[ r0      * 128 + r] = pr0;
                g_dz[(r0 + 1) * 128 + r] = pr1;
            }

            grid_barrier(base + (++bno));   // B: dz complete

            // ---- row-owner: RK4 stage update ----
            if (tid < 32) {
                int h0 = tid << 2;
                float4 dz = *(const float4*)(g_dz + r * 128 + h0);
                float4 kq = *(float4*)(kacc + h0);
                float4 zq = *(float4*)(zs + h0);
                float kw = (stage == 0 || stage == 3) ? 1.0f : 2.0f;
                kq.x = fmaf(kw, dz.x, kq.x); kq.y = fmaf(kw, dz.y, kq.y);
                kq.z = fmaf(kw, dz.z, kq.z); kq.w = fmaf(kw, dz.w, kq.w);
                if (stage < 3) {
                    float aa = (stage == 2) ? 1.0f : 0.5f;
                    float4 yq;
                    yq.x = fmaf(aa, dz.x, zq.x); yq.y = fmaf(aa, dz.y, zq.y);
                    yq.z = fmaf(aa, dz.z, zq.z); yq.w = fmaf(aa, dz.w, zq.w);
                    *(float4*)(ys + h0) = yq;
                    *(float4*)(kacc + h0) = kq;
                } else {
                    const float c6 = 1.0f / 6.0f;
                    zq.x = fmaf(c6, kq.x, zq.x); zq.y = fmaf(c6, kq.y, zq.y);
                    zq.z = fmaf(c6, kq.z, zq.z); zq.w = fmaf(c6, kq.w, zq.w);
                    *(float4*)(zs + h0) = zq;
                    *(float4*)(ys + h0) = zq;
                    *(float4*)(kacc + h0) = make_float4(0.f, 0.f, 0.f, 0.f);
                }
            }
            __syncthreads();
        }
    }

    // ---- readout: out[r] = sigmoid(z @ Wr + br) ----
    if (tid < 32) {
        float part = 0.0f;
        #pragma unroll
        for (int h = tid; h < 128; h += 32)
            part = fmaf(zs[h], Wr[h], part);
        #pragma unroll
        for (int off = 16; off >= 1; off >>= 1)
            part += __shfl_down_sync(0xffffffffu, part, off);
        if (tid == 0)
            out[r] = 1.0f / (1.0f + __expf(-(part + br[0])));
    }
}

extern "C" void kernel_launch(void* const* d_in, const int* in_sizes, int n_in,
                              void* d_out, int out_size)
{
    const float* coeffs = (const float*)d_in[0];
    const float* W1 = (const float*)d_in[1];
    const float* b1 = (const float*)d_in[2];
    const float* W2 = (const float*)d_in[3];
    const float* b2 = (const float*)d_in[4];
    const float* W3 = (const float*)d_in[5];
    const float* b3 = (const float*)d_in[6];
    const float* Wi = (const float*)d_in[7];
    const float* bi = (const float*)d_in[8];
    const float* Wr = (const float*)d_in[9];
    const float* br = (const float*)d_in[10];
    float* out = (float*)d_out;

    cudaFuncSetAttribute(cde_kernel,
                         cudaFuncAttributeMaxDynamicSharedMemorySize, SMEM_BYTES);
    cde_kernel<<<NCTAS, NT, SMEM_BYTES>>>(coeffs, W1, b1, W2, b2, W3, b3,
                                          Wi, bi, Wr, br, out);
}